// round 6
// baseline (speedup 1.0000x reference)
#include <cuda_runtime.h>
#include <cuda_pipeline.h>
#include <math.h>

// EIRNN: T=128, B=64, IN=512, H=1024, L=3, NE=819, alpha=0.2
// Persistent kernel: 128 CTAs x 512 threads, CTA owns 8 output cols (all layers).
// Weights resident in SMEM [k][8]; activations k-major [K][64] in global scratch.
// Compute: packed fma.rn.f32x2, 4x4 reg tiles, 16-way K-split across warps,
// cp.async double-buffered 64-k staging chunks, SMEM reduction + store bounce.

#define NBLK 128
#define NTHR 512
#define ALPHA 0.2f
#define NE 819

// SMEM float offsets
#define W_IN0 0          // 512*8
#define W_RC0 4096       // 1024*8
#define W_IN1 12288
#define W_RC1 20480
#define W_IN2 28672
#define W_RC2 36864
#define ASMO  45056      // 2 x (64x64) staging, reused as 16x512 reduction
#define HBUF  53248      // 64x9 bounce (h)
#define OBUF  53824      // 64x9 bounce (masked out)
#define SMEM_FLOATS 54400
#define SMEM_BYTES (SMEM_FLOATS * 4)   // 217600

#define AH_OFF 8388608       // T*B*H
#define AH_L   8454144       // 129*B*H
#define BH     65536         // B*H

__device__ float g_xT[128 * 512 * 64];     // inputs transposed [t][k][b]
__device__ float g_h[2][3][1024 * 64];     // h double buffer, [c][b]
__device__ float g_ci[2][1024 * 64];       // cell input for layers 1,2
__device__ unsigned g_cnt;
__device__ volatile unsigned g_gen;

__global__ void xt_kernel(const float* __restrict__ x) {
    int idx = blockIdx.x * 256 + threadIdx.x;     // [t][k][b] linear
    int b = idx & 63;
    int k = (idx >> 6) & 511;
    int t = idx >> 15;
    g_xT[idx] = x[t * 32768 + b * 512 + k];
}

__device__ __forceinline__ void grid_barrier() {
    __syncthreads();
    if (threadIdx.x == 0) {
        __threadfence();
        unsigned gen = g_gen;
        if (atomicAdd(&g_cnt, 1u) == NBLK - 1) {
            g_cnt = 0;
            __threadfence();
            g_gen = gen + 1u;
        } else {
            while (g_gen == gen) __nanosleep(32);
        }
        __threadfence();
    }
    __syncthreads();
}

// load one weight slice (8 rows) into SMEM as [k][8], abs + optional Dale sign
__device__ void load_w(const float* __restrict__ g, int K, float* dst, int dale, int tid) {
    for (int idx = tid; idx < 8 * K; idx += NTHR) {
        int i = idx / K, k = idx - i * K;
        float w = fabsf(g[i * K + k]);
        if (dale && k >= NE) w = -w;
        dst[k * 8 + i] = w;
    }
}

__device__ __forceinline__ void issue_chunk(float* dst, const float* src, int tid) {
    __pipeline_memcpy_async(dst + tid * 4, src + tid * 4, 16);
    __pipeline_memcpy_async(dst + 2048 + tid * 4, src + 2048 + tid * 4, 16);
    __pipeline_commit();
}

#define FMA2(ACC, WP, AV) \
    asm("fma.rn.f32x2 %0, %1, %2, %0;" : "+l"(ACC) : "l"(WP), "l"(AV))

__global__ void __launch_bounds__(NTHR, 1)
eirnn_kernel(const float* __restrict__ hid,
             const float* __restrict__ win0,
             const float* __restrict__ win1,
             const float* __restrict__ win2,
             const float* __restrict__ wrec,
             const float* __restrict__ bg,
             float* __restrict__ out) {
    extern __shared__ float smem[];
    float* Asm = smem + ASMO;
    const int tid = threadIdx.x;
    // accumulation map: warp = k-slice (16-way); lane -> 2 col-quads x 16 batch-quads
    const int ks = tid >> 5;
    const int lane = tid & 31;
    const int c4 = (lane & 1) * 4;
    const int b4 = (lane >> 1) * 4;
    // reduction/epilogue map: 1 (col,batch) output per thread
    const int ce = tid >> 6;         // 0..7
    const int be = tid & 63;         // 0..63
    const int c0 = blockIdx.x * 8;
    const int cge = c0 + ce;

    // ---- prologue: weights -> SMEM ----
    load_w(win0 + c0 * 512, 512, smem + W_IN0, 0, tid);
    load_w(win1 + c0 * 1024, 1024, smem + W_IN1, 0, tid);
    load_w(win2 + c0 * 1024, 1024, smem + W_IN2, 0, tid);
    load_w(wrec + 0 * 1048576 + c0 * 1024, 1024, smem + W_RC0, 1, tid);
    load_w(wrec + 1 * 1048576 + c0 * 1024, 1024, smem + W_RC1, 1, tid);
    load_w(wrec + 2 * 1048576 + c0 * 1024, 1024, smem + W_RC2, 1, tid);

    // ---- prologue: h init (transposed) + all_hiddens[:,0] ----
    for (int idx = tid; idx < 8 * 64; idx += NTHR) {
        int i = idx >> 6, b = idx & 63;
        float hv = hid[b * 1024 + c0 + i];
#pragma unroll
        for (int l = 0; l < 3; l++) {
            g_h[0][l][(c0 + i) * 64 + b] = hv;
            out[AH_OFF + l * AH_L + b * 1024 + c0 + i] = hv;
        }
    }

    const float emask = (cge < NE) ? 1.f : 0.f;
    float bias_r[3];
#pragma unroll
    for (int l = 0; l < 3; l++) bias_r[l] = bg[l * 1024 + cge];
    float vr[3] = {0.f, 0.f, 0.f};

    const int ffOff[3] = {W_IN0, W_IN1, W_IN2};
    const int rcOff[3] = {W_RC0, W_RC1, W_RC2};

    for (int t = 0; t < 128; t++) {
        int p = t & 1;
        const float* ff = g_xT + t * 32768;
        int Kf = 512;
#pragma unroll 1
        for (int l = 0; l < 3; l++) {
            grid_barrier();
            const float* rec = g_h[p][l];
            const float* wf = smem + ffOff[l];
            const float* wr = smem + rcOff[l];
            const int nf = Kf >> 6;
            const int nch = nf + 16;

            unsigned long long acc[4][2];
#pragma unroll
            for (int cc = 0; cc < 4; cc++) { acc[cc][0] = 0ull; acc[cc][1] = 0ull; }

            issue_chunk(Asm, ff, tid);
#pragma unroll 1
            for (int cch = 0; cch < nch; cch++) {
                __pipeline_wait_prior(0);
                __syncthreads();
                if (cch + 1 < nch) {
                    const float* s = (cch + 1 < nf) ? ff + (cch + 1) * 4096
                                                    : rec + (cch + 1 - nf) * 4096;
                    issue_chunk(Asm + ((cch + 1) & 1) * 4096, s, tid);
                }
                const float* Ac = Asm + (cch & 1) * 4096;
                const float* Wc = (cch < nf) ? wf + cch * 512 : wr + (cch - nf) * 512;
#pragma unroll
                for (int i = 0; i < 4; i++) {
                    int k = ks + 16 * i;
                    float4 w = *(const float4*)(Wc + k * 8 + c4);
                    ulonglong2 a = *(const ulonglong2*)(Ac + k * 64 + b4);
                    unsigned long long wp;
                    asm("mov.b64 %0, {%1, %1};" : "=l"(wp) : "f"(w.x));
                    FMA2(acc[0][0], wp, a.x);
                    FMA2(acc[0][1], wp, a.y);
                    asm("mov.b64 %0, {%1, %1};" : "=l"(wp) : "f"(w.y));
                    FMA2(acc[1][0], wp, a.x);
                    FMA2(acc[1][1], wp, a.y);
                    asm("mov.b64 %0, {%1, %1};" : "=l"(wp) : "f"(w.z));
                    FMA2(acc[2][0], wp, a.x);
                    FMA2(acc[2][1], wp, a.y);
                    asm("mov.b64 %0, {%1, %1};" : "=l"(wp) : "f"(w.w));
                    FMA2(acc[3][0], wp, a.x);
                    FMA2(acc[3][1], wp, a.y);
                }
            }
            __syncthreads();   // staging reads done; reuse Asm for reduction

            float* red = Asm;
#pragma unroll
            for (int cc = 0; cc < 4; cc++) {
                ulonglong2 v;
                v.x = acc[cc][0];
                v.y = acc[cc][1];
                *(ulonglong2*)(red + ks * 512 + (c4 + cc) * 64 + b4) = v;
            }
            __syncthreads();

            float s = bias_r[l];
#pragma unroll
            for (int q = 0; q < 16; q++) s += red[q * 512 + ce * 64 + be];
            vr[l] = (1.f - ALPHA) * vr[l] + ALPHA * s;
            float h = fmaxf(vr[l], 0.f);
            g_h[1 - p][l][cge * 64 + be] = h;
            smem[HBUF + be * 9 + ce] = h;
            float ci = h * emask;
            if (l < 2) g_ci[l][cge * 64 + be] = ci;
            else       smem[OBUF + be * 9 + ce] = ci;
            __syncthreads();

            // coalesced b-major stores via bounce
            {
                int cw = tid & 7, bw = tid >> 3;
                out[AH_OFF + l * AH_L + (t + 1) * BH + bw * 1024 + c0 + cw] =
                    smem[HBUF + bw * 9 + cw];
                if (l == 2)
                    out[t * BH + bw * 1024 + c0 + cw] = smem[OBUF + bw * 9 + cw];
            }

            ff = g_ci[l < 2 ? l : 0];
            Kf = 1024;
        }
    }
}

extern "C" void kernel_launch(void* const* d_in, const int* in_sizes, int n_in,
                              void* d_out, int out_size) {
    const float* x    = (const float*)d_in[0];
    const float* hid  = (const float*)d_in[1];
    const float* win0 = (const float*)d_in[2];
    const float* win1 = (const float*)d_in[3];
    const float* win2 = (const float*)d_in[4];
    const float* wrec = (const float*)d_in[5];
    const float* bg   = (const float*)d_in[6];
    float* out = (float*)d_out;

    cudaFuncSetAttribute(eirnn_kernel, cudaFuncAttributeMaxDynamicSharedMemorySize, SMEM_BYTES);

    xt_kernel<<<128 * 512 * 64 / 256, 256>>>(x);
    eirnn_kernel<<<NBLK, NTHR, SMEM_BYTES>>>(hid, win0, win1, win2, wrec, bg, out);
}

// round 7
// speedup vs baseline: 1.4548x; 1.4548x over previous
#include <cuda_runtime.h>
#include <math.h>

#define NBLK 128
#define NTHR 512
#define ALPHA 0.2f
#define NE 819

// SMEM float offsets: per-layer weights [k][8] (ff rows then Dale-signed rec rows)
#define WOFF0 0          // 1536*8
#define WOFF1 12288      // 2048*8
#define WOFF2 28672      // 2048*8
#define REDO  45056      // 16 x 64 x 8 reduction
#define HBUF  53248      // 64*9
#define OBUF  53824      // 64*9
#define SMEM_BYTES (54400 * 4)

#define AH_OFF 8388608
#define AH_L   8454144
#define BH     65536

__device__ float g_xT[128 * 512 * 64];
__device__ float g_h[2][3][1024 * 64];
__device__ float g_ci[2][2][1024 * 64];
__device__ int g_cnt8[8];
__device__ int g_init;

__global__ void xt_kernel(const float* __restrict__ x) {
    int idx = blockIdx.x * 256 + threadIdx.x;
    int b = idx & 63, k = (idx >> 6) & 511, t = idx >> 15;
    g_xT[idx] = x[t * 32768 + b * 512 + k];
    if (idx < 8) g_cnt8[idx] = 0;
    if (idx == 8) g_init = 0;
}

__device__ __forceinline__ void wait_ge(const int* p, int val) {
    int v;
    do {
        asm volatile("ld.global.cg.b32 %0, [%1];" : "=r"(v) : "l"(p));
        if (v >= val) break;
        __nanosleep(64);
    } while (true);
    __threadfence();
}

__device__ void load_w(const float* __restrict__ g, int K, float* dst, int dale, int tid) {
    for (int idx = tid; idx < 8 * K; idx += NTHR) {
        int i = idx / K, k = idx - i * K;
        float v = fabsf(g[i * K + k]);
        if (dale && k >= NE) v = -v;
        dst[k * 8 + i] = v;
    }
}

#define FMA2(A, W, X) asm("fma.rn.f32x2 %0, %1, %2, %0;" : "+l"(A) : "l"(W), "l"(X))
#define ADD2(A, B)    asm("add.rn.f32x2 %0, %0, %1;" : "+l"(A) : "l"(B))

// 8 cols x 4 batches per thread; this (warp,s) slice covers k = kb + 32*i.
__device__ __forceinline__ void accum(unsigned long long acc[4][4],
                                      const float* __restrict__ act,
                                      const float* __restrict__ wsm,
                                      int kb, int b4, int n) {
    const float4* ap = (const float4*)(act + kb * 64 + b4);
    const ulonglong2* wp = (const ulonglong2*)(wsm + kb * 8);
#pragma unroll 4
    for (int i = 0; i < n; i++) {
        float4 a = __ldcg(ap);
        ap += 512;
        ulonglong2 w01 = wp[0];
        ulonglong2 w23 = wp[1];
        wp += 64;
        unsigned long long ab[4];
        asm("mov.b64 %0, {%1, %1};" : "=l"(ab[0]) : "f"(a.x));
        asm("mov.b64 %0, {%1, %1};" : "=l"(ab[1]) : "f"(a.y));
        asm("mov.b64 %0, {%1, %1};" : "=l"(ab[2]) : "f"(a.z));
        asm("mov.b64 %0, {%1, %1};" : "=l"(ab[3]) : "f"(a.w));
#pragma unroll
        for (int b = 0; b < 4; b++) {
            FMA2(acc[0][b], w01.x, ab[b]);
            FMA2(acc[1][b], w01.y, ab[b]);
            FMA2(acc[2][b], w23.x, ab[b]);
            FMA2(acc[3][b], w23.y, ab[b]);
        }
    }
}

__global__ void __launch_bounds__(NTHR, 1)
eirnn_kernel(const float* __restrict__ hid,
             const float* __restrict__ win0,
             const float* __restrict__ win1,
             const float* __restrict__ win2,
             const float* __restrict__ wrec,
             const float* __restrict__ bg,
             float* __restrict__ out) {
    extern __shared__ float smem[];
    float* red = smem + REDO;
    const int tid = threadIdx.x;
    const int w = tid >> 5, lane = tid & 31;
    const int s = lane & 1, b4 = (lane >> 1) * 4;
    const int kb = 2 * w + s;
    const int ce = tid >> 6, be = tid & 63;
    const int c0 = blockIdx.x * 8, cge = c0 + ce;

    load_w(win0 + c0 * 512, 512, smem + WOFF0, 0, tid);
    load_w(wrec + 0 * 1048576 + c0 * 1024, 1024, smem + WOFF0 + 512 * 8, 1, tid);
    load_w(win1 + c0 * 1024, 1024, smem + WOFF1, 0, tid);
    load_w(wrec + 1 * 1048576 + c0 * 1024, 1024, smem + WOFF1 + 1024 * 8, 1, tid);
    load_w(win2 + c0 * 1024, 1024, smem + WOFF2, 0, tid);
    load_w(wrec + 2 * 1048576 + c0 * 1024, 1024, smem + WOFF2 + 1024 * 8, 1, tid);

    for (int idx = tid; idx < 8 * 64; idx += NTHR) {
        int i = idx >> 6, b = idx & 63;
        float hv = hid[b * 1024 + c0 + i];
#pragma unroll
        for (int l = 0; l < 3; l++) {
            g_h[0][l][(c0 + i) * 64 + b] = hv;
            out[AH_OFF + l * AH_L + b * 1024 + c0 + i] = hv;
        }
    }
    __threadfence();
    __syncthreads();
    if (tid == 0) atomicAdd(&g_init, 1);
    wait_ge(&g_init, NBLK);

    const float emask = (cge < NE) ? 1.f : 0.f;
    float bias_r[3];
#pragma unroll
    for (int l = 0; l < 3; l++) bias_r[l] = bg[l * 1024 + cge];
    float vr[3] = {0.f, 0.f, 0.f};
    const int wOff[3] = {WOFF0, WOFF1, WOFF2};

    int n = 0;
    for (int t = 0; t < 128; t++) {
        int tp = t & 1;
#pragma unroll 1
        for (int l = 0; l < 3; l++) {
            const float* wl = smem + wOff[l];
            const int Kf = l ? 1024 : 512;
            unsigned long long acc[4][4];
#pragma unroll
            for (int i = 0; i < 4; i++)
#pragma unroll
                for (int b = 0; b < 4; b++) acc[i][b] = 0ull;

            if (n >= 3) wait_ge(&g_cnt8[(n - 3) & 7], NBLK);
            accum(acc, g_h[tp][l], wl + Kf * 8, kb, b4, 32);
            if (l > 0) wait_ge(&g_cnt8[(n - 1) & 7], NBLK);
            accum(acc, l ? g_ci[tp][l - 1] : g_xT + t * 32768, wl, kb, b4, Kf >> 5);

            // combine s=0/1 within warp, even lanes write slice partials
#pragma unroll
            for (int cp = 0; cp < 4; cp++)
#pragma unroll
                for (int b = 0; b < 4; b++) {
                    unsigned long long o = __shfl_xor_sync(0xffffffffu, acc[cp][b], 1);
                    ADD2(acc[cp][b], o);
                }
            if (s == 0) {
#pragma unroll
                for (int b = 0; b < 4; b++) {
                    int uu = b4 + b, up = uu ^ ((uu >> 2) & 3);
                    ulonglong2* dst = (ulonglong2*)(red + w * 512 + up * 8);
                    ulonglong2 v1, v2;
                    v1.x = acc[0][b]; v1.y = acc[1][b];
                    v2.x = acc[2][b]; v2.y = acc[3][b];
                    dst[0] = v1;
                    dst[1] = v2;
                }
            }
            __syncthreads();

            const int ue = be ^ ((be >> 2) & 3);
            float sum = bias_r[l];
#pragma unroll
            for (int q = 0; q < 16; q++) sum += red[q * 512 + ue * 8 + ce];
            vr[l] = (1.f - ALPHA) * vr[l] + ALPHA * sum;
            float h = fmaxf(vr[l], 0.f);
            g_h[1 - tp][l][cge * 64 + be] = h;
            smem[HBUF + be * 9 + ce] = h;
            float ci = h * emask;
            if (l < 2) g_ci[tp][l][cge * 64 + be] = ci;
            else       smem[OBUF + be * 9 + ce] = ci;
            __threadfence();
            __syncthreads();

            int cw = tid & 7, bw = tid >> 3;
            out[AH_OFF + l * AH_L + (t + 1) * BH + bw * 1024 + c0 + cw] =
                smem[HBUF + bw * 9 + cw];
            if (l == 2)
                out[t * BH + bw * 1024 + c0 + cw] = smem[OBUF + bw * 9 + cw];
            if (tid == 0) {
                int r = atomicAdd(&g_cnt8[n & 7], 1);
                if (r == NBLK - 1 && n >= 4) atomicExch(&g_cnt8[(n + 4) & 7], 0);
            }
            n++;
        }
    }
}

extern "C" void kernel_launch(void* const* d_in, const int* in_sizes, int n_in,
                              void* d_out, int out_size) {
    const float* x    = (const float*)d_in[0];
    const float* hid  = (const float*)d_in[1];
    const float* win0 = (const float*)d_in[2];
    const float* win1 = (const float*)d_in[3];
    const float* win2 = (const float*)d_in[4];
    const float* wrec = (const float*)d_in[5];
    const float* bg   = (const float*)d_in[6];
    float* out = (float*)d_out;

    cudaFuncSetAttribute(eirnn_kernel, cudaFuncAttributeMaxDynamicSharedMemorySize, SMEM_BYTES);
    xt_kernel<<<128 * 512 * 64 / 256, 256>>>(x);
    eirnn_kernel<<<NBLK, NTHR, SMEM_BYTES>>>(hid, win0, win1, win2, wrec, bg, out);
}